// round 4
// baseline (speedup 1.0000x reference)
#include <cuda_runtime.h>
#include <cuda_bf16.h>

// QuantumAttention: B=2, S=1024, EMBED=256, HEADS=64, DK=4.
// Pipeline: y = x@W^T (3x) -> quantum expvals (closed form, products of cosines)
// -> per-head attention (dk=4, S=1024) -> output (B,S,256).
//
// Quantum closed form: z_w = cos(p_w)*cos(ang_w + p_w)
//   E = ( z1*z2*z3, z0*z1, z0*z1*z2, z0*z1*z2*z3 )

typedef unsigned long long u64;

#define NB 2
#define NS 1024
#define NE 256
#define NH 64

// Scratch: quantum expvals, layout [b][h][s][4]
__device__ float g_qe[NB * NH * NS * 4];
__device__ float g_ke[NB * NH * NS * 4];
__device__ float g_ve[NB * NH * NS * 4];

// ---------------- f32x2 packed helpers (sm_103a) ----------------
__device__ __forceinline__ u64 pk2(float lo, float hi) {
    u64 r; asm("mov.b64 %0, {%1, %2};" : "=l"(r) : "f"(lo), "f"(hi)); return r;
}
__device__ __forceinline__ void upk2(u64 v, float& lo, float& hi) {
    asm("mov.b64 {%0, %1}, %2;" : "=f"(lo), "=f"(hi) : "l"(v));
}
__device__ __forceinline__ u64 fma2_(u64 a, u64 b, u64 c) {
    u64 d; asm("fma.rn.f32x2 %0, %1, %2, %3;" : "=l"(d) : "l"(a), "l"(b), "l"(c)); return d;
}
__device__ __forceinline__ u64 mul2_(u64 a, u64 b) {
    u64 d; asm("mul.rn.f32x2 %0, %1, %2;" : "=l"(d) : "l"(a), "l"(b)); return d;
}
__device__ __forceinline__ u64 add2_(u64 a, u64 b) {
    u64 d; asm("add.rn.f32x2 %0, %1, %2;" : "=l"(d) : "l"(a), "l"(b)); return d;
}
__device__ __forceinline__ float ex2_(float x) {
    float r; asm("ex2.approx.ftz.f32 %0, %1;" : "=f"(r) : "f"(x)); return r;
}

// ---------------- Kernel A: QKV projection + quantum epilogue ----------------
// C(2048 x 768) = X(2048 x 256) @ [Wq;Wk;Wv]^T, tiled 64x64, BK=16,
// 256 threads, 4x4 microtile per thread. Each thread's 4 output columns are
// one aligned head group -> quantum transform applied in registers.
__global__ __launch_bounds__(256) void qkvq_kernel(
    const float* __restrict__ x,  const float* __restrict__ Wq,
    const float* __restrict__ Wk, const float* __restrict__ Wv,
    const float* __restrict__ params)
{
    __shared__ float As[16][64];
    __shared__ float Bs[16][64];

    const int tid = threadIdx.x;
    const int tx = tid & 15;
    const int ty = tid >> 4;
    const int bm = blockIdx.x;           // 0..31 : row tile (64 rows)
    const int gc0 = blockIdx.y * 64;     // 0..704: global output-col base

    const float* W;
    float* dst;
    if (gc0 < 256)      { W = Wq; dst = g_qe; }
    else if (gc0 < 512) { W = Wk; dst = g_ke; }
    else                { W = Wv; dst = g_ve; }
    const int nc0 = gc0 & 255;           // col base within this matrix

    // cooperative load indices: 64 rows x 16 cols per tile, float4 per thread
    const int lr = tid >> 2;             // 0..63
    const int lc = (tid & 3) << 2;       // 0,4,8,12
    const float* xrow = x + (bm * 64 + lr) * NE + lc;
    const float* wrow = W + (nc0 + lr) * NE + lc;

    float c[4][4];
#pragma unroll
    for (int i = 0; i < 4; i++)
#pragma unroll
        for (int j = 0; j < 4; j++) c[i][j] = 0.0f;

    for (int k0 = 0; k0 < NE; k0 += 16) {
        float4 av = *reinterpret_cast<const float4*>(xrow + k0);
        float4 bv = *reinterpret_cast<const float4*>(wrow + k0);
        As[lc + 0][lr] = av.x; As[lc + 1][lr] = av.y;
        As[lc + 2][lr] = av.z; As[lc + 3][lr] = av.w;
        Bs[lc + 0][lr] = bv.x; Bs[lc + 1][lr] = bv.y;
        Bs[lc + 2][lr] = bv.z; Bs[lc + 3][lr] = bv.w;
        __syncthreads();
#pragma unroll
        for (int k = 0; k < 16; k++) {
            float4 a = *reinterpret_cast<const float4*>(&As[k][ty * 4]);
            float4 b = *reinterpret_cast<const float4*>(&Bs[k][tx * 4]);
            c[0][0] += a.x * b.x; c[0][1] += a.x * b.y; c[0][2] += a.x * b.z; c[0][3] += a.x * b.w;
            c[1][0] += a.y * b.x; c[1][1] += a.y * b.y; c[1][2] += a.y * b.z; c[1][3] += a.y * b.w;
            c[2][0] += a.z * b.x; c[2][1] += a.z * b.y; c[2][2] += a.z * b.z; c[2][3] += a.z * b.w;
            c[3][0] += a.w * b.x; c[3][1] += a.w * b.y; c[3][2] += a.w * b.z; c[3][3] += a.w * b.w;
        }
        __syncthreads();
    }

    // quantum epilogue: each thread's 4 cols = one head's 4 angles
    const float p0 = params[0], p1 = params[1], p2 = params[2], p3 = params[3];
    const float cp0 = cosf(p0), cp1 = cosf(p1), cp2 = cosf(p2), cp3 = cosf(p3);
    const int h = (nc0 >> 2) + tx;       // head index 0..63

#pragma unroll
    for (int i = 0; i < 4; i++) {
        const int r = bm * 64 + ty * 4 + i;
        const int bb = r >> 10;
        const int s = r & 1023;
        float z0 = cp0 * cosf(c[i][0] + p0);
        float z1 = cp1 * cosf(c[i][1] + p1);
        float z2 = cp2 * cosf(c[i][2] + p2);
        float z3 = cp3 * cosf(c[i][3] + p3);
        float e1 = z0 * z1;
        float e2 = e1 * z2;
        float e3 = e2 * z3;
        float e0 = (z1 * z2) * z3;
        reinterpret_cast<float4*>(dst)[(bb * NH + h) * NS + s] =
            make_float4(e0, e1, e2, e3);
    }
}

// ---------------- Kernel B: per-head attention (dk=4, S=1024) ----------------
// Grid (128, 4): block = one (b,h) x 256-query chunk. K,V for the head live in
// smem, repacked so two consecutive keys' d-components form f32x2 operands.
// |score| <= 2 -> exp-sum safe without max subtraction. 0.5/sqrt->log2e folded
// into q so exp(score) = ex2(dot).
__global__ __launch_bounds__(256) void attn_kernel(float* __restrict__ out)
{
    __shared__ float4 KA[512];  // {k0[j],k0[j+1],k1[j],k1[j+1]}
    __shared__ float4 KB[512];  // {k2[j],k2[j+1],k3[j],k3[j+1]}
    __shared__ float4 VA[512];
    __shared__ float4 VB[512];

    const int bh = blockIdx.x;          // 0..127
    const int b  = bh >> 6;
    const int h  = bh & 63;
    const int tid = threadIdx.x;

    const float4* KE = reinterpret_cast<const float4*>(g_ke) + bh * NS;
    const float4* VE = reinterpret_cast<const float4*>(g_ve) + bh * NS;
    for (int pp = tid; pp < 512; pp += 256) {
        float4 k0 = KE[2 * pp], k1 = KE[2 * pp + 1];
        KA[pp] = make_float4(k0.x, k1.x, k0.y, k1.y);
        KB[pp] = make_float4(k0.z, k1.z, k0.w, k1.w);
        float4 v0 = VE[2 * pp], v1 = VE[2 * pp + 1];
        VA[pp] = make_float4(v0.x, v1.x, v0.y, v1.y);
        VB[pp] = make_float4(v0.z, v1.z, v0.w, v1.w);
    }
    __syncthreads();

    const int sq = blockIdx.y * 256 + tid;
    float4 q = reinterpret_cast<const float4*>(g_qe)[bh * NS + sq];
    const float sc = 0.5f * 1.4426950408889634f;  // (1/sqrt(dk)) * log2(e)
    const u64 q0 = pk2(q.x * sc, q.x * sc);
    const u64 q1 = pk2(q.y * sc, q.y * sc);
    const u64 q2 = pk2(q.z * sc, q.z * sc);
    const u64 q3 = pk2(q.w * sc, q.w * sc);

    u64 den = 0ULL;
    u64 acc0 = 0ULL, acc1 = 0ULL, acc2 = 0ULL, acc3 = 0ULL;

#pragma unroll 4
    for (int jj = 0; jj < 512; jj++) {
        float4 a  = KA[jj];
        float4 bb = KB[jj];
        u64 s01 = mul2_(q0, pk2(a.x, a.y));
        s01 = fma2_(q1, pk2(a.z, a.w), s01);
        s01 = fma2_(q2, pk2(bb.x, bb.y), s01);
        s01 = fma2_(q3, pk2(bb.z, bb.w), s01);
        float s0, s1; upk2(s01, s0, s1);
        u64 e01 = pk2(ex2_(s0), ex2_(s1));
        den = add2_(den, e01);
        float4 va = VA[jj];
        float4 vb = VB[jj];
        acc0 = fma2_(e01, pk2(va.x, va.y), acc0);
        acc1 = fma2_(e01, pk2(va.z, va.w), acc1);
        acc2 = fma2_(e01, pk2(vb.x, vb.y), acc2);
        acc3 = fma2_(e01, pk2(vb.z, vb.w), acc3);
    }

    float dl, dh; upk2(den, dl, dh);
    const float inv = 1.0f / (dl + dh);
    float l, hi_;
    upk2(acc0, l, hi_); float o0 = (l + hi_) * inv;
    upk2(acc1, l, hi_); float o1 = (l + hi_) * inv;
    upk2(acc2, l, hi_); float o2 = (l + hi_) * inv;
    upk2(acc3, l, hi_); float o3 = (l + hi_) * inv;

    // out[b][sq][h*4 + d]
    reinterpret_cast<float4*>(out)[(b * NS + sq) * NH + h] =
        make_float4(o0, o1, o2, o3);
}

// ---------------- launch ----------------
extern "C" void kernel_launch(void* const* d_in, const int* in_sizes, int n_in,
                              void* d_out, int out_size) {
    const float* x      = (const float*)d_in[0];
    const float* Wq     = (const float*)d_in[1];
    const float* Wk     = (const float*)d_in[2];
    const float* Wv     = (const float*)d_in[3];
    const float* params = (const float*)d_in[4];
    float* out = (float*)d_out;

    qkvq_kernel<<<dim3(32, 12), 256>>>(x, Wq, Wk, Wv, params);
    attn_kernel<<<dim3(128, 4), 256>>>(out);
}

// round 5
// speedup vs baseline: 1.0597x; 1.0597x over previous
#include <cuda_runtime.h>
#include <cuda_bf16.h>

// QuantumAttention: B=2, S=1024, EMBED=256, HEADS=64, DK=4.
// Pipeline: y = x@W^T (3x) -> quantum expvals (closed form, products of cosines)
// -> per-head attention (dk=4, S=1024) -> output (B,S,256).
//
// Quantum closed form: z_w = cos(p_w)*cos(ang_w + p_w)
//   E = ( z1*z2*z3, z0*z1, z0*z1*z2, z0*z1*z2*z3 )

typedef unsigned long long u64;

#define NB 2
#define NS 1024
#define NE 256
#define NH 64

// Scratch: quantum expvals, layout [b][h][s][4]
__device__ float g_qe[NB * NH * NS * 4];
__device__ float g_ke[NB * NH * NS * 4];
__device__ float g_ve[NB * NH * NS * 4];

// ---------------- f32x2 packed helpers (sm_103a) ----------------
__device__ __forceinline__ u64 pk2(float lo, float hi) {
    u64 r; asm("mov.b64 %0, {%1, %2};" : "=l"(r) : "f"(lo), "f"(hi)); return r;
}
__device__ __forceinline__ void upk2(u64 v, float& lo, float& hi) {
    asm("mov.b64 {%0, %1}, %2;" : "=f"(lo), "=f"(hi) : "l"(v));
}
__device__ __forceinline__ u64 fma2_(u64 a, u64 b, u64 c) {
    u64 d; asm("fma.rn.f32x2 %0, %1, %2, %3;" : "=l"(d) : "l"(a), "l"(b), "l"(c)); return d;
}
__device__ __forceinline__ u64 mul2_(u64 a, u64 b) {
    u64 d; asm("mul.rn.f32x2 %0, %1, %2;" : "=l"(d) : "l"(a), "l"(b)); return d;
}
__device__ __forceinline__ u64 add2_(u64 a, u64 b) {
    u64 d; asm("add.rn.f32x2 %0, %1, %2;" : "=l"(d) : "l"(a), "l"(b)); return d;
}
__device__ __forceinline__ float ex2_(float x) {
    float r; asm("ex2.approx.ftz.f32 %0, %1;" : "=f"(r) : "f"(x)); return r;
}

// ---------------- Kernel A: QKV projection + quantum epilogue ----------------
// C(2048 x 768) = X(2048 x 256) @ [Wq;Wk;Wv]^T, tiled 64x64, BK=16,
// 256 threads, 4x4 microtile per thread. Each thread's 4 output columns are
// one aligned head group -> quantum transform applied in registers.
__global__ __launch_bounds__(256) void qkvq_kernel(
    const float* __restrict__ x,  const float* __restrict__ Wq,
    const float* __restrict__ Wk, const float* __restrict__ Wv,
    const float* __restrict__ params)
{
    __shared__ float As[16][64];
    __shared__ float Bs[16][64];

    const int tid = threadIdx.x;
    const int tx = tid & 15;
    const int ty = tid >> 4;
    const int bm = blockIdx.x;           // 0..31 : row tile (64 rows)
    const int gc0 = blockIdx.y * 64;     // 0..704: global output-col base

    const float* W;
    float* dst;
    if (gc0 < 256)      { W = Wq; dst = g_qe; }
    else if (gc0 < 512) { W = Wk; dst = g_ke; }
    else                { W = Wv; dst = g_ve; }
    const int nc0 = gc0 & 255;           // col base within this matrix

    // cooperative load indices: 64 rows x 16 cols per tile, float4 per thread
    const int lr = tid >> 2;             // 0..63
    const int lc = (tid & 3) << 2;       // 0,4,8,12
    const float* xrow = x + (bm * 64 + lr) * NE + lc;
    const float* wrow = W + (nc0 + lr) * NE + lc;

    float c[4][4];
#pragma unroll
    for (int i = 0; i < 4; i++)
#pragma unroll
        for (int j = 0; j < 4; j++) c[i][j] = 0.0f;

    for (int k0 = 0; k0 < NE; k0 += 16) {
        float4 av = *reinterpret_cast<const float4*>(xrow + k0);
        float4 bv = *reinterpret_cast<const float4*>(wrow + k0);
        As[lc + 0][lr] = av.x; As[lc + 1][lr] = av.y;
        As[lc + 2][lr] = av.z; As[lc + 3][lr] = av.w;
        Bs[lc + 0][lr] = bv.x; Bs[lc + 1][lr] = bv.y;
        Bs[lc + 2][lr] = bv.z; Bs[lc + 3][lr] = bv.w;
        __syncthreads();
#pragma unroll
        for (int k = 0; k < 16; k++) {
            float4 a = *reinterpret_cast<const float4*>(&As[k][ty * 4]);
            float4 b = *reinterpret_cast<const float4*>(&Bs[k][tx * 4]);
            c[0][0] += a.x * b.x; c[0][1] += a.x * b.y; c[0][2] += a.x * b.z; c[0][3] += a.x * b.w;
            c[1][0] += a.y * b.x; c[1][1] += a.y * b.y; c[1][2] += a.y * b.z; c[1][3] += a.y * b.w;
            c[2][0] += a.z * b.x; c[2][1] += a.z * b.y; c[2][2] += a.z * b.z; c[2][3] += a.z * b.w;
            c[3][0] += a.w * b.x; c[3][1] += a.w * b.y; c[3][2] += a.w * b.z; c[3][3] += a.w * b.w;
        }
        __syncthreads();
    }

    // quantum epilogue: each thread's 4 cols = one head's 4 angles
    const float p0 = params[0], p1 = params[1], p2 = params[2], p3 = params[3];
    const float cp0 = cosf(p0), cp1 = cosf(p1), cp2 = cosf(p2), cp3 = cosf(p3);
    const int h = (nc0 >> 2) + tx;       // head index 0..63

#pragma unroll
    for (int i = 0; i < 4; i++) {
        const int r = bm * 64 + ty * 4 + i;
        const int bb = r >> 10;
        const int s = r & 1023;
        float z0 = cp0 * cosf(c[i][0] + p0);
        float z1 = cp1 * cosf(c[i][1] + p1);
        float z2 = cp2 * cosf(c[i][2] + p2);
        float z3 = cp3 * cosf(c[i][3] + p3);
        float e1 = z0 * z1;
        float e2 = e1 * z2;
        float e3 = e2 * z3;
        float e0 = (z1 * z2) * z3;
        reinterpret_cast<float4*>(dst)[(bb * NH + h) * NS + s] =
            make_float4(e0, e1, e2, e3);
    }
}

// ---------------- Kernel B: per-head attention (dk=4, S=1024) ----------------
// Grid 128 (one block per (b,h)), 256 threads, 4 queries per thread.
// K,V live in smem PRE-PACKED as f32x2 operand pairs (ulonglong2), so each
// LDS.128 feeds fma.rn.f32x2 directly with no repack movs, and each K/V load
// is amortized over 4 queries.
// |score| <= 2 -> exp-sum safe without max subtraction. 0.5/sqrt->log2e folded
// into q so exp(score) = ex2(dot).
__global__ __launch_bounds__(256) void attn_kernel(float* __restrict__ out)
{
    __shared__ ulonglong2 KU[512];  // { pk(k0.x,k1.x), pk(k0.y,k1.y) }
    __shared__ ulonglong2 KW[512];  // { pk(k0.z,k1.z), pk(k0.w,k1.w) }
    __shared__ ulonglong2 VU[512];
    __shared__ ulonglong2 VW[512];

    const int bh = blockIdx.x;          // 0..127
    const int b  = bh >> 6;
    const int h  = bh & 63;
    const int tid = threadIdx.x;

    const float4* KE = reinterpret_cast<const float4*>(g_ke) + bh * NS;
    const float4* VE = reinterpret_cast<const float4*>(g_ve) + bh * NS;
#pragma unroll
    for (int t = 0; t < 2; t++) {
        int pp = tid + t * 256;
        float4 k0 = KE[2 * pp], k1 = KE[2 * pp + 1];
        KU[pp] = make_ulonglong2(pk2(k0.x, k1.x), pk2(k0.y, k1.y));
        KW[pp] = make_ulonglong2(pk2(k0.z, k1.z), pk2(k0.w, k1.w));
        float4 v0 = VE[2 * pp], v1 = VE[2 * pp + 1];
        VU[pp] = make_ulonglong2(pk2(v0.x, v1.x), pk2(v0.y, v1.y));
        VW[pp] = make_ulonglong2(pk2(v0.z, v1.z), pk2(v0.w, v1.w));
    }
    __syncthreads();

    const float sc = 0.5f * 1.4426950408889634f;  // (1/sqrt(dk)) * log2(e)
    u64 q0[4], q1[4], q2[4], q3[4];
    u64 den[4], a0[4], a1[4], a2[4], a3[4];
#pragma unroll
    for (int qi = 0; qi < 4; qi++) {
        const int sq = qi * 256 + tid;
        float4 q = reinterpret_cast<const float4*>(g_qe)[bh * NS + sq];
        q0[qi] = pk2(q.x * sc, q.x * sc);
        q1[qi] = pk2(q.y * sc, q.y * sc);
        q2[qi] = pk2(q.z * sc, q.z * sc);
        q3[qi] = pk2(q.w * sc, q.w * sc);
        den[qi] = 0ULL;
        a0[qi] = 0ULL; a1[qi] = 0ULL; a2[qi] = 0ULL; a3[qi] = 0ULL;
    }

#pragma unroll 2
    for (int jj = 0; jj < 512; jj++) {
        const ulonglong2 ka = KU[jj];
        const ulonglong2 kb = KW[jj];
        const ulonglong2 va = VU[jj];
        const ulonglong2 vb = VW[jj];
#pragma unroll
        for (int qi = 0; qi < 4; qi++) {
            u64 s = mul2_(q0[qi], ka.x);
            s = fma2_(q1[qi], ka.y, s);
            s = fma2_(q2[qi], kb.x, s);
            s = fma2_(q3[qi], kb.y, s);
            float s0, s1; upk2(s, s0, s1);
            u64 e = pk2(ex2_(s0), ex2_(s1));
            den[qi] = add2_(den[qi], e);
            a0[qi] = fma2_(e, va.x, a0[qi]);
            a1[qi] = fma2_(e, va.y, a1[qi]);
            a2[qi] = fma2_(e, vb.x, a2[qi]);
            a3[qi] = fma2_(e, vb.y, a3[qi]);
        }
    }

#pragma unroll
    for (int qi = 0; qi < 4; qi++) {
        const int sq = qi * 256 + tid;
        float dl, dh; upk2(den[qi], dl, dh);
        const float inv = 1.0f / (dl + dh);
        float l, hi_;
        upk2(a0[qi], l, hi_); float o0 = (l + hi_) * inv;
        upk2(a1[qi], l, hi_); float o1 = (l + hi_) * inv;
        upk2(a2[qi], l, hi_); float o2 = (l + hi_) * inv;
        upk2(a3[qi], l, hi_); float o3 = (l + hi_) * inv;
        // out[b][sq][h*4 + d]
        reinterpret_cast<float4*>(out)[(b * NS + sq) * NH + h] =
            make_float4(o0, o1, o2, o3);
    }
}

// ---------------- launch ----------------
extern "C" void kernel_launch(void* const* d_in, const int* in_sizes, int n_in,
                              void* d_out, int out_size) {
    const float* x      = (const float*)d_in[0];
    const float* Wq     = (const float*)d_in[1];
    const float* Wk     = (const float*)d_in[2];
    const float* Wv     = (const float*)d_in[3];
    const float* params = (const float*)d_in[4];
    float* out = (float*)d_out;

    qkvq_kernel<<<dim3(32, 12), 256>>>(x, Wq, Wk, Wv, params);
    attn_kernel<<<dim3(128, 1), 256>>>(out);
}

// round 6
// speedup vs baseline: 1.1311x; 1.0674x over previous
#include <cuda_runtime.h>
#include <cuda_bf16.h>

// QuantumAttention: B=2, S=1024, EMBED=256, HEADS=64, DK=4.
// Pipeline: y = x@W^T (3x) -> quantum expvals (closed form, products of cosines)
// -> per-head attention (dk=4, S=1024) -> output (B,S,256).
//
// Quantum closed form: z_w = cos(p_w)*cos(ang_w + p_w)
//   E = ( z1*z2*z3, z0*z1, z0*z1*z2, z0*z1*z2*z3 )

typedef unsigned long long u64;

#define NB 2
#define NS 1024
#define NE 256
#define NH 64

// Scratch: quantum expvals, layout [b][h][s][4]
__device__ float g_qe[NB * NH * NS * 4];
__device__ float g_ke[NB * NH * NS * 4];
__device__ float g_ve[NB * NH * NS * 4];

// ---------------- f32x2 packed helpers (sm_103a) ----------------
__device__ __forceinline__ u64 pk2(float lo, float hi) {
    u64 r; asm("mov.b64 %0, {%1, %2};" : "=l"(r) : "f"(lo), "f"(hi)); return r;
}
__device__ __forceinline__ void upk2(u64 v, float& lo, float& hi) {
    asm("mov.b64 {%0, %1}, %2;" : "=f"(lo), "=f"(hi) : "l"(v));
}
__device__ __forceinline__ u64 fma2_(u64 a, u64 b, u64 c) {
    u64 d; asm("fma.rn.f32x2 %0, %1, %2, %3;" : "=l"(d) : "l"(a), "l"(b), "l"(c)); return d;
}
__device__ __forceinline__ u64 mul2_(u64 a, u64 b) {
    u64 d; asm("mul.rn.f32x2 %0, %1, %2;" : "=l"(d) : "l"(a), "l"(b)); return d;
}
__device__ __forceinline__ u64 add2_(u64 a, u64 b) {
    u64 d; asm("add.rn.f32x2 %0, %1, %2;" : "=l"(d) : "l"(a), "l"(b)); return d;
}
__device__ __forceinline__ float ex2_(float x) {
    float r; asm("ex2.approx.ftz.f32 %0, %1;" : "=f"(r) : "f"(x)); return r;
}

// ---------------- Kernel A: QKV projection + quantum epilogue ----------------
// C(2048 x 768) = X(2048 x 256) @ [Wq;Wk;Wv]^T, tiled 64x64, BK=16,
// 256 threads, 4x4 microtile per thread, f32x2-packed accumulators
// (B-tile pre-packed in smem as f32x2 operand pairs). Each thread's 4 output
// columns are one aligned head group -> quantum transform in registers.
__global__ __launch_bounds__(256) void qkvq_kernel(
    const float* __restrict__ x,  const float* __restrict__ Wq,
    const float* __restrict__ Wk, const float* __restrict__ Wv,
    const float* __restrict__ params)
{
    __shared__ float As[16][64];
    __shared__ u64 BsP[16][32];   // packed pairs: BsP[k][c] = (B[k][2c], B[k][2c+1])

    const int tid = threadIdx.x;
    const int tx = tid & 15;
    const int ty = tid >> 4;
    const int bm = blockIdx.x;           // 0..31 : row tile (64 rows)
    const int gc0 = blockIdx.y * 64;     // 0..704: global output-col base

    const float* W;
    float* dst;
    if (gc0 < 256)      { W = Wq; dst = g_qe; }
    else if (gc0 < 512) { W = Wk; dst = g_ke; }
    else                { W = Wv; dst = g_ve; }
    const int nc0 = gc0 & 255;           // col base within this matrix

    // cooperative load indices: 64 rows x 16 cols per tile, float4 per thread
    const int lr = tid >> 2;             // 0..63
    const int lc = (tid & 3) << 2;       // 0,4,8,12
    const float* xrow = x + (bm * 64 + lr) * NE + lc;
    const float* wrow = W + (nc0 + lr) * NE + lc;

    u64 c01[4], c23[4];
#pragma unroll
    for (int i = 0; i < 4; i++) { c01[i] = 0ULL; c23[i] = 0ULL; }

    for (int k0 = 0; k0 < NE; k0 += 16) {
        float4 av = *reinterpret_cast<const float4*>(xrow + k0);
        float4 bv = *reinterpret_cast<const float4*>(wrow + k0);
        As[lc + 0][lr] = av.x; As[lc + 1][lr] = av.y;
        As[lc + 2][lr] = av.z; As[lc + 3][lr] = av.w;
        // B row lr, cols lc..lc+3 -> transposed packed pairs
        BsP[lc + 0][lr >> 1] = 0;  // placeholder overwritten below (avoid warning)
        __syncthreads();  // (placeholder sync removed below)
        __syncthreads();
#pragma unroll
        for (int k = 0; k < 16; k++) {
            float4 a = *reinterpret_cast<const float4*>(&As[k][ty * 4]);
            ulonglong2 bp = *reinterpret_cast<const ulonglong2*>(&BsP[k][tx * 2]);
            u64 ax = pk2(a.x, a.x), ay = pk2(a.y, a.y);
            u64 az = pk2(a.z, a.z), aw = pk2(a.w, a.w);
            c01[0] = fma2_(ax, bp.x, c01[0]); c23[0] = fma2_(ax, bp.y, c23[0]);
            c01[1] = fma2_(ay, bp.x, c01[1]); c23[1] = fma2_(ay, bp.y, c23[1]);
            c01[2] = fma2_(az, bp.x, c01[2]); c23[2] = fma2_(az, bp.y, c23[2]);
            c01[3] = fma2_(aw, bp.x, c01[3]); c23[3] = fma2_(aw, bp.y, c23[3]);
        }
        __syncthreads();
    }

    // quantum epilogue: each thread's 4 cols = one head's 4 angles
    const float p0 = params[0], p1 = params[1], p2 = params[2], p3 = params[3];
    const float cp0 = cosf(p0), cp1 = cosf(p1), cp2 = cosf(p2), cp3 = cosf(p3);
    const int h = (nc0 >> 2) + tx;       // head index 0..63

#pragma unroll
    for (int i = 0; i < 4; i++) {
        const int r = bm * 64 + ty * 4 + i;
        const int bb = r >> 10;
        const int s = r & 1023;
        float a0, a1, a2, a3;
        upk2(c01[i], a0, a1);
        upk2(c23[i], a2, a3);
        float z0 = cp0 * __cosf(a0 + p0);
        float z1 = cp1 * __cosf(a1 + p1);
        float z2 = cp2 * __cosf(a2 + p2);
        float z3 = cp3 * __cosf(a3 + p3);
        float e1 = z0 * z1;
        float e2 = e1 * z2;
        float e3 = e2 * z3;
        float e0 = (z1 * z2) * z3;
        reinterpret_cast<float4*>(dst)[(bb * NH + h) * NS + s] =
            make_float4(e0, e1, e2, e3);
    }
}

// Fixed B fill: separate function body needed the store before syncs; we do the
// packing inline in the loop above via this corrected kernel. (The placeholder
// line is overwritten here.)
// NOTE: The actual B packing happens in the loader below — see qkvq_kernel2.
// To keep a single kernel, we re-implement the fill properly:

__global__ __launch_bounds__(256) void qkvq_kernel2(
    const float* __restrict__ x,  const float* __restrict__ Wq,
    const float* __restrict__ Wk, const float* __restrict__ Wv,
    const float* __restrict__ params)
{
    __shared__ float As[16][64];
    __shared__ u64 BsP[16][32];

    const int tid = threadIdx.x;
    const int tx = tid & 15;
    const int ty = tid >> 4;
    const int bm = blockIdx.x;
    const int gc0 = blockIdx.y * 64;

    const float* W;
    float* dst;
    if (gc0 < 256)      { W = Wq; dst = g_qe; }
    else if (gc0 < 512) { W = Wk; dst = g_ke; }
    else                { W = Wv; dst = g_ve; }
    const int nc0 = gc0 & 255;

    const int lr = tid >> 2;             // 0..63
    const int lc = (tid & 3) << 2;       // 0,4,8,12
    const float* xrow = x + (bm * 64 + lr) * NE + lc;
    const float* wrow = W + (nc0 + lr) * NE + lc;

    u64 c01[4], c23[4];
#pragma unroll
    for (int i = 0; i < 4; i++) { c01[i] = 0ULL; c23[i] = 0ULL; }

    for (int k0 = 0; k0 < NE; k0 += 16) {
        float4 av = *reinterpret_cast<const float4*>(xrow + k0);
        float4 bv = *reinterpret_cast<const float4*>(wrow + k0);
        As[lc + 0][lr] = av.x; As[lc + 1][lr] = av.y;
        As[lc + 2][lr] = av.z; As[lc + 3][lr] = av.w;
        // B[row=lr (out-col), col=lc+j (k)] -> BsP[k][out-col pair]
        // pair index = lr>>1, lane = lr&1. Two threads cooperate per pair via
        // 32-bit halves: store as two 32-bit words.
        {
            float* bw = reinterpret_cast<float*>(&BsP[0][0]);
            // BsP[k][p] occupies 2 floats at linear index (k*32 + p)*2 + lane
            const int p = lr >> 1, lane = lr & 1;
            bw[((lc + 0) * 32 + p) * 2 + lane] = bv.x;
            bw[((lc + 1) * 32 + p) * 2 + lane] = bv.y;
            bw[((lc + 2) * 32 + p) * 2 + lane] = bv.z;
            bw[((lc + 3) * 32 + p) * 2 + lane] = bv.w;
        }
        __syncthreads();
#pragma unroll
        for (int k = 0; k < 16; k++) {
            float4 a = *reinterpret_cast<const float4*>(&As[k][ty * 4]);
            ulonglong2 bp = *reinterpret_cast<const ulonglong2*>(&BsP[k][tx * 2]);
            u64 ax = pk2(a.x, a.x), ay = pk2(a.y, a.y);
            u64 az = pk2(a.z, a.z), aw = pk2(a.w, a.w);
            c01[0] = fma2_(ax, bp.x, c01[0]); c23[0] = fma2_(ax, bp.y, c23[0]);
            c01[1] = fma2_(ay, bp.x, c01[1]); c23[1] = fma2_(ay, bp.y, c23[1]);
            c01[2] = fma2_(az, bp.x, c01[2]); c23[2] = fma2_(az, bp.y, c23[2]);
            c01[3] = fma2_(aw, bp.x, c01[3]); c23[3] = fma2_(aw, bp.y, c23[3]);
        }
        __syncthreads();
    }

    const float p0 = params[0], p1 = params[1], p2 = params[2], p3 = params[3];
    const float cp0 = cosf(p0), cp1 = cosf(p1), cp2 = cosf(p2), cp3 = cosf(p3);
    const int h = (nc0 >> 2) + tx;

#pragma unroll
    for (int i = 0; i < 4; i++) {
        const int r = bm * 64 + ty * 4 + i;
        const int bb = r >> 10;
        const int s = r & 1023;
        float a0, a1, a2, a3;
        upk2(c01[i], a0, a1);
        upk2(c23[i], a2, a3);
        float z0 = cp0 * __cosf(a0 + p0);
        float z1 = cp1 * __cosf(a1 + p1);
        float z2 = cp2 * __cosf(a2 + p2);
        float z3 = cp3 * __cosf(a3 + p3);
        float e1 = z0 * z1;
        float e2 = e1 * z2;
        float e3 = e2 * z3;
        float e0 = (z1 * z2) * z3;
        reinterpret_cast<float4*>(dst)[(bb * NH + h) * NS + s] =
            make_float4(e0, e1, e2, e3);
    }
}

// ---------------- Kernel B: per-head attention (dk=4, S=1024) ----------------
// Grid (128, 2): block = (b,h) x half the queries. 256 threads, 2 queries per
// thread. K,V in smem PRE-PACKED as f32x2 operand pairs; each LDS.128 feeds
// fma.rn.f32x2 directly. ~2 CTAs/SM -> 16 warps to hide the score-chain + ex2
// latency. |score| <= 2 -> no max subtraction; 0.5/sqrt*log2e folded into q.
__global__ __launch_bounds__(256) void attn_kernel(float* __restrict__ out)
{
    __shared__ ulonglong2 KU[512];  // { pk(k0.x,k1.x), pk(k0.y,k1.y) }
    __shared__ ulonglong2 KW[512];  // { pk(k0.z,k1.z), pk(k0.w,k1.w) }
    __shared__ ulonglong2 VU[512];
    __shared__ ulonglong2 VW[512];

    const int bh = blockIdx.x;          // 0..127
    const int b  = bh >> 6;
    const int h  = bh & 63;
    const int tid = threadIdx.x;

    const float4* KE = reinterpret_cast<const float4*>(g_ke) + bh * NS;
    const float4* VE = reinterpret_cast<const float4*>(g_ve) + bh * NS;
#pragma unroll
    for (int t = 0; t < 2; t++) {
        int pp = tid + t * 256;
        float4 k0 = KE[2 * pp], k1 = KE[2 * pp + 1];
        KU[pp] = make_ulonglong2(pk2(k0.x, k1.x), pk2(k0.y, k1.y));
        KW[pp] = make_ulonglong2(pk2(k0.z, k1.z), pk2(k0.w, k1.w));
        float4 v0 = VE[2 * pp], v1 = VE[2 * pp + 1];
        VU[pp] = make_ulonglong2(pk2(v0.x, v1.x), pk2(v0.y, v1.y));
        VW[pp] = make_ulonglong2(pk2(v0.z, v1.z), pk2(v0.w, v1.w));
    }
    __syncthreads();

    const float sc = 0.5f * 1.4426950408889634f;  // (1/sqrt(dk)) * log2(e)
    u64 q0[2], q1[2], q2[2], q3[2];
    u64 den[2], a0[2], a1[2], a2[2], a3[2];
#pragma unroll
    for (int qi = 0; qi < 2; qi++) {
        const int sq = blockIdx.y * 512 + qi * 256 + tid;
        float4 q = reinterpret_cast<const float4*>(g_qe)[bh * NS + sq];
        q0[qi] = pk2(q.x * sc, q.x * sc);
        q1[qi] = pk2(q.y * sc, q.y * sc);
        q2[qi] = pk2(q.z * sc, q.z * sc);
        q3[qi] = pk2(q.w * sc, q.w * sc);
        den[qi] = 0ULL;
        a0[qi] = 0ULL; a1[qi] = 0ULL; a2[qi] = 0ULL; a3[qi] = 0ULL;
    }

#pragma unroll 4
    for (int jj = 0; jj < 512; jj++) {
        const ulonglong2 ka = KU[jj];
        const ulonglong2 kb = KW[jj];
        const ulonglong2 va = VU[jj];
        const ulonglong2 vb = VW[jj];
#pragma unroll
        for (int qi = 0; qi < 2; qi++) {
            // 3-level score tree
            u64 sA = mul2_(q0[qi], ka.x);
            u64 sB = mul2_(q2[qi], kb.x);
            sA = fma2_(q1[qi], ka.y, sA);
            sB = fma2_(q3[qi], kb.y, sB);
            u64 s = add2_(sA, sB);
            float s0, s1; upk2(s, s0, s1);
            u64 e = pk2(ex2_(s0), ex2_(s1));
            den[qi] = add2_(den[qi], e);
            a0[qi] = fma2_(e, va.x, a0[qi]);
            a1[qi] = fma2_(e, va.y, a1[qi]);
            a2[qi] = fma2_(e, vb.x, a2[qi]);
            a3[qi] = fma2_(e, vb.y, a3[qi]);
        }
    }

#pragma unroll
    for (int qi = 0; qi < 2; qi++) {
        const int sq = blockIdx.y * 512 + qi * 256 + tid;
        float dl, dh; upk2(den[qi], dl, dh);
        const float inv = 1.0f / (dl + dh);
        float l, hi_;
        upk2(a0[qi], l, hi_); float o0 = (l + hi_) * inv;
        upk2(a1[qi], l, hi_); float o1 = (l + hi_) * inv;
        upk2(a2[qi], l, hi_); float o2 = (l + hi_) * inv;
        upk2(a3[qi], l, hi_); float o3 = (l + hi_) * inv;
        // out[b][sq][h*4 + d]
        reinterpret_cast<float4*>(out)[(b * NS + sq) * NH + h] =
            make_float4(o0, o1, o2, o3);
    }
}

// ---------------- launch ----------------
extern "C" void kernel_launch(void* const* d_in, const int* in_sizes, int n_in,
                              void* d_out, int out_size) {
    const float* x      = (const float*)d_in[0];
    const float* Wq     = (const float*)d_in[1];
    const float* Wk     = (const float*)d_in[2];
    const float* Wv     = (const float*)d_in[3];
    const float* params = (const float*)d_in[4];
    float* out = (float*)d_out;

    qkvq_kernel2<<<dim3(32, 12), 256>>>(x, Wq, Wk, Wv, params);
    attn_kernel<<<dim3(128, 2), 256>>>(out);
}

// round 7
// speedup vs baseline: 1.1510x; 1.0176x over previous
#include <cuda_runtime.h>
#include <cuda_bf16.h>

// QuantumAttention: B=2, S=1024, EMBED=256, HEADS=64, DK=4.
// Pipeline: y = x@W^T (3x) -> quantum expvals (closed form, products of cosines)
// -> per-head attention (dk=4, S=1024) -> output (B,S,256).
//
// Quantum closed form: z_w = cos(p_w)*cos(ang_w + p_w)
//   E = ( z1*z2*z3, z0*z1, z0*z1*z2, z0*z1*z2*z3 )
//
// Attention softmax: |E|<=1 -> |score|<=2 -> exp in [0.14, 7.4], sum <= 7.6K.
// No running max needed => softmax numerator/denominator are PURE SUMS over
// keys => key-split parallel decomposition with additive combine.

typedef unsigned long long u64;

#define NB 2
#define NS 1024
#define NE 256
#define NH 64
#define NQ (NB * NH * NS)   // 131072 total queries

// Scratch: quantum expvals, layout [b][h][s][4]
__device__ float g_qe[NB * NH * NS * 4];
__device__ float g_ke[NB * NH * NS * 4];
__device__ float g_ve[NB * NH * NS * 4];
// Key-split partials: numerator float4 and denominator per (ksplit, query)
__device__ float4 g_pacc[2][NQ];
__device__ float  g_pden[2][NQ];

// ---------------- f32x2 packed helpers (sm_103a) ----------------
__device__ __forceinline__ u64 pk2(float lo, float hi) {
    u64 r; asm("mov.b64 %0, {%1, %2};" : "=l"(r) : "f"(lo), "f"(hi)); return r;
}
__device__ __forceinline__ void upk2(u64 v, float& lo, float& hi) {
    asm("mov.b64 {%0, %1}, %2;" : "=f"(lo), "=f"(hi) : "l"(v));
}
__device__ __forceinline__ u64 fma2_(u64 a, u64 b, u64 c) {
    u64 d; asm("fma.rn.f32x2 %0, %1, %2, %3;" : "=l"(d) : "l"(a), "l"(b), "l"(c)); return d;
}
__device__ __forceinline__ u64 mul2_(u64 a, u64 b) {
    u64 d; asm("mul.rn.f32x2 %0, %1, %2;" : "=l"(d) : "l"(a), "l"(b)); return d;
}
__device__ __forceinline__ u64 add2_(u64 a, u64 b) {
    u64 d; asm("add.rn.f32x2 %0, %1, %2;" : "=l"(d) : "l"(a), "l"(b)); return d;
}
__device__ __forceinline__ float ex2_(float x) {
    float r; asm("ex2.approx.ftz.f32 %0, %1;" : "=f"(r) : "f"(x)); return r;
}

// ---------------- Kernel A: QKV projection + quantum epilogue ----------------
// C(2048 x 768) = X(2048 x 256) @ [Wq;Wk;Wv]^T, tiled 64x64, BK=16,
// 256 threads, 4x4 microtile per thread, f32x2-packed accumulators with the
// B-tile pre-packed in smem as f32x2 operand pairs. Register double-buffered
// global loads. Each thread's 4 output columns are one aligned head group ->
// quantum transform in registers.
__global__ __launch_bounds__(256) void qkvq_kernel(
    const float* __restrict__ x,  const float* __restrict__ Wq,
    const float* __restrict__ Wk, const float* __restrict__ Wv,
    const float* __restrict__ params)
{
    __shared__ float As[16][64];
    __shared__ u64 BsP[16][32];   // BsP[k][c] = pk2(B[k][2c], B[k][2c+1])

    const int tid = threadIdx.x;
    const int tx = tid & 15;
    const int ty = tid >> 4;
    const int bm = blockIdx.x;           // 0..31 : row tile (64 rows)
    const int gc0 = blockIdx.y * 64;     // 0..704: global output-col base

    const float* W;
    float* dst;
    if (gc0 < 256)      { W = Wq; dst = g_qe; }
    else if (gc0 < 512) { W = Wk; dst = g_ke; }
    else                { W = Wv; dst = g_ve; }
    const int nc0 = gc0 & 255;           // col base within this matrix

    // cooperative load indices: 64 rows x 16 cols per tile, float4 per thread
    const int lr = tid >> 2;             // 0..63
    const int lc = (tid & 3) << 2;       // 0,4,8,12
    const float* xrow = x + (bm * 64 + lr) * NE + lc;
    const float* wrow = W + (nc0 + lr) * NE + lc;

    u64 c01[4], c23[4];
#pragma unroll
    for (int i = 0; i < 4; i++) { c01[i] = 0ULL; c23[i] = 0ULL; }

    float4 av = *reinterpret_cast<const float4*>(xrow);
    float4 bv = *reinterpret_cast<const float4*>(wrow);

    for (int k0 = 0; k0 < NE; k0 += 16) {
        As[lc + 0][lr] = av.x; As[lc + 1][lr] = av.y;
        As[lc + 2][lr] = av.z; As[lc + 3][lr] = av.w;
        // B[out-col=lr][k=lc+j] -> BsP[k][lr>>1] halves (two threads per pair)
        {
            float* bw = reinterpret_cast<float*>(&BsP[0][0]);
            const int base = lr;  // ((k)*32 + (lr>>1))*2 + (lr&1) == k*64 + lr
            bw[(lc + 0) * 64 + base] = bv.x;
            bw[(lc + 1) * 64 + base] = bv.y;
            bw[(lc + 2) * 64 + base] = bv.z;
            bw[(lc + 3) * 64 + base] = bv.w;
        }
        __syncthreads();
        if (k0 + 16 < NE) {
            av = *reinterpret_cast<const float4*>(xrow + k0 + 16);
            bv = *reinterpret_cast<const float4*>(wrow + k0 + 16);
        }
#pragma unroll
        for (int k = 0; k < 16; k++) {
            float4 a = *reinterpret_cast<const float4*>(&As[k][ty * 4]);
            ulonglong2 bp = *reinterpret_cast<const ulonglong2*>(&BsP[k][tx * 2]);
            u64 ax = pk2(a.x, a.x), ay = pk2(a.y, a.y);
            u64 az = pk2(a.z, a.z), aw = pk2(a.w, a.w);
            c01[0] = fma2_(ax, bp.x, c01[0]); c23[0] = fma2_(ax, bp.y, c23[0]);
            c01[1] = fma2_(ay, bp.x, c01[1]); c23[1] = fma2_(ay, bp.y, c23[1]);
            c01[2] = fma2_(az, bp.x, c01[2]); c23[2] = fma2_(az, bp.y, c23[2]);
            c01[3] = fma2_(aw, bp.x, c01[3]); c23[3] = fma2_(aw, bp.y, c23[3]);
        }
        __syncthreads();
    }

    // quantum epilogue: each thread's 4 cols = one head's 4 angles
    const float p0 = params[0], p1 = params[1], p2 = params[2], p3 = params[3];
    const float cp0 = cosf(p0), cp1 = cosf(p1), cp2 = cosf(p2), cp3 = cosf(p3);
    const int h = (nc0 >> 2) + tx;       // head index 0..63

#pragma unroll
    for (int i = 0; i < 4; i++) {
        const int r = bm * 64 + ty * 4 + i;
        const int bb = r >> 10;
        const int s = r & 1023;
        float a0, a1, a2, a3;
        upk2(c01[i], a0, a1);
        upk2(c23[i], a2, a3);
        float z0 = cp0 * __cosf(a0 + p0);
        float z1 = cp1 * __cosf(a1 + p1);
        float z2 = cp2 * __cosf(a2 + p2);
        float z3 = cp3 * __cosf(a3 + p3);
        float e1 = z0 * z1;
        float e2 = e1 * z2;
        float e3 = e2 * z3;
        float e0 = (z1 * z2) * z3;
        reinterpret_cast<float4*>(dst)[(bb * NH + h) * NS + s] =
            make_float4(e0, e1, e2, e3);
    }
}

// ---------------- Kernel B: attention partials (key-split) ----------------
// Grid (128, 2, 2): block = (b,h) x query-half x key-half. 256 threads,
// 2 queries per thread, 256 key-pairs in smem pre-packed as f32x2 operand
// pairs. Writes partial numerator/denominator sums to scratch (additive
// softmax decomposition -- no max subtraction needed since |score| <= 2).
__global__ __launch_bounds__(256) void attn_part_kernel()
{
    __shared__ ulonglong2 KU[256];  // { pk(k0.x,k1.x), pk(k0.y,k1.y) }
    __shared__ ulonglong2 KW[256];  // { pk(k0.z,k1.z), pk(k0.w,k1.w) }
    __shared__ ulonglong2 VU[256];
    __shared__ ulonglong2 VW[256];

    const int bh = blockIdx.x;          // 0..127
    const int ks = blockIdx.z;          // key split 0/1
    const int tid = threadIdx.x;

    const float4* KE = reinterpret_cast<const float4*>(g_ke) + bh * NS + ks * 512;
    const float4* VE = reinterpret_cast<const float4*>(g_ve) + bh * NS + ks * 512;
    {
        const int pp = tid;             // 256 pairs, one per thread
        float4 k0 = KE[2 * pp], k1 = KE[2 * pp + 1];
        KU[pp] = make_ulonglong2(pk2(k0.x, k1.x), pk2(k0.y, k1.y));
        KW[pp] = make_ulonglong2(pk2(k0.z, k1.z), pk2(k0.w, k1.w));
        float4 v0 = VE[2 * pp], v1 = VE[2 * pp + 1];
        VU[pp] = make_ulonglong2(pk2(v0.x, v1.x), pk2(v0.y, v1.y));
        VW[pp] = make_ulonglong2(pk2(v0.z, v1.z), pk2(v0.w, v1.w));
    }
    __syncthreads();

    const float sc = 0.5f * 1.4426950408889634f;  // (1/sqrt(dk)) * log2(e)
    u64 q0[2], q1[2], q2[2], q3[2];
    u64 den[2], a0[2], a1[2], a2[2], a3[2];
#pragma unroll
    for (int qi = 0; qi < 2; qi++) {
        const int sq = blockIdx.y * 512 + qi * 256 + tid;
        float4 q = reinterpret_cast<const float4*>(g_qe)[bh * NS + sq];
        q0[qi] = pk2(q.x * sc, q.x * sc);
        q1[qi] = pk2(q.y * sc, q.y * sc);
        q2[qi] = pk2(q.z * sc, q.z * sc);
        q3[qi] = pk2(q.w * sc, q.w * sc);
        den[qi] = 0ULL;
        a0[qi] = 0ULL; a1[qi] = 0ULL; a2[qi] = 0ULL; a3[qi] = 0ULL;
    }

#pragma unroll 4
    for (int jj = 0; jj < 256; jj++) {
        const ulonglong2 ka = KU[jj];
        const ulonglong2 kb = KW[jj];
        const ulonglong2 va = VU[jj];
        const ulonglong2 vb = VW[jj];
#pragma unroll
        for (int qi = 0; qi < 2; qi++) {
            // 3-level score tree
            u64 sA = mul2_(q0[qi], ka.x);
            u64 sB = mul2_(q2[qi], kb.x);
            sA = fma2_(q1[qi], ka.y, sA);
            sB = fma2_(q3[qi], kb.y, sB);
            u64 s = add2_(sA, sB);
            float s0, s1; upk2(s, s0, s1);
            u64 e = pk2(ex2_(s0), ex2_(s1));
            den[qi] = add2_(den[qi], e);
            a0[qi] = fma2_(e, va.x, a0[qi]);
            a1[qi] = fma2_(e, va.y, a1[qi]);
            a2[qi] = fma2_(e, vb.x, a2[qi]);
            a3[qi] = fma2_(e, vb.y, a3[qi]);
        }
    }

#pragma unroll
    for (int qi = 0; qi < 2; qi++) {
        const int sq = blockIdx.y * 512 + qi * 256 + tid;
        const int qidx = bh * NS + sq;
        float dl, dh; upk2(den[qi], dl, dh);
        float l, hi_;
        upk2(a0[qi], l, hi_); float n0 = l + hi_;
        upk2(a1[qi], l, hi_); float n1 = l + hi_;
        upk2(a2[qi], l, hi_); float n2 = l + hi_;
        upk2(a3[qi], l, hi_); float n3 = l + hi_;
        g_pacc[ks][qidx] = make_float4(n0, n1, n2, n3);
        g_pden[ks][qidx] = dl + dh;
    }
}

// ---------------- Kernel C: combine key-split partials ----------------
__global__ __launch_bounds__(256) void attn_combine_kernel(float* __restrict__ out)
{
    const int idx = blockIdx.x * 256 + threadIdx.x;  // query index 0..NQ-1
    const int bh = idx >> 10;
    const int sq = idx & 1023;
    const int b = bh >> 6;
    const int h = bh & 63;

    float4 n0 = g_pacc[0][idx];
    float4 n1 = g_pacc[1][idx];
    const float inv = 1.0f / (g_pden[0][idx] + g_pden[1][idx]);
    reinterpret_cast<float4*>(out)[(b * NS + sq) * NH + h] =
        make_float4((n0.x + n1.x) * inv, (n0.y + n1.y) * inv,
                    (n0.z + n1.z) * inv, (n0.w + n1.w) * inv);
}

// ---------------- launch ----------------
extern "C" void kernel_launch(void* const* d_in, const int* in_sizes, int n_in,
                              void* d_out, int out_size) {
    const float* x      = (const float*)d_in[0];
    const float* Wq     = (const float*)d_in[1];
    const float* Wk     = (const float*)d_in[2];
    const float* Wv     = (const float*)d_in[3];
    const float* params = (const float*)d_in[4];
    float* out = (float*)d_out;

    qkvq_kernel<<<dim3(32, 12), 256>>>(x, Wq, Wk, Wv, params);
    attn_part_kernel<<<dim3(128, 2, 2), 256>>>();
    attn_combine_kernel<<<NQ / 256, 256>>>(out);
}